// round 14
// baseline (speedup 1.0000x reference)
#include <cuda_runtime.h>
#include <cuda_bf16.h>

// Problem constants (fixed by the reference setup_inputs)
#define BB 64
#define SS 512
#define HH 768
#define WW 256      // MAX_WORD_LEN
#define WE 300
#define OUTW (HH + WE)   // 1068 floats
#define HV  (HH/4)       // 192 float4
#define WV  (WE/4)       // 75 float4

// Two words per 256-thread CTA (8192 CTAs). Lower half-block handles word w0,
// upper half handles w1 = w0+1 — both in FULL parallel (no serialization).
// Shared head done once: threads 0..127 load all 512 sorted token_ids (int4
// each) and count three fields in one pass: c=#<w0, d=#==w0, e=#==w1
// (10-bit packed; lo1 = c+d since sorted). One redux + one barrier serves
// both words -> token L2 traffic and barrier cost halve vs 1 word/CTA.
// Each half then runs the depth-4 predicated prefetch mean (MLP~8/warp),
// streaming loads/stores throughout.
__global__ __launch_bounds__(256)
void embeddings_fused_kernel(const float* __restrict__ hidden,
                             const float* __restrict__ w2v,
                             const int*   __restrict__ token_ids,
                             const int*   __restrict__ word_ids,
                             float*       __restrict__ out)
{
    const int gi  = blockIdx.x;            // 0 .. B*W/2 - 1
    const int b   = gi >> 7;               // / (WW/2)
    const int w0  = (gi & 127) << 1;       // even word
    const int tid = threadIdx.x;           // 0 .. 255
    const int h   = tid & 127;             // index within half-block
    const int up  = tid >> 7;              // 0 = word w0, 1 = word w0+1
    const int w   = w0 + up;
    const int bw  = b * WW + w;

    __shared__ int s_part[4];

    // ---- per-half w2v gather starts immediately (overlaps the count) ----
    const int wid = __ldg(&word_ids[bw]);
    const bool hasw = (h < WV);
    float4 gv;
    if (hasw) {
        gv = __ldg(reinterpret_cast<const float4*>(w2v + (size_t)wid * WE) + h);
    }

    // ---- shared parallel count (lower half only): 128 x int4 = 512 ids ----
    if (up == 0) {
        const int4 tv = __ldg(reinterpret_cast<const int4*>(token_ids + b * SS) + h);
        int c = (tv.x < w0) + (tv.y < w0) + (tv.z < w0) + (tv.w < w0);          // #< w0
        int d = (tv.x == w0) + (tv.y == w0) + (tv.z == w0) + (tv.w == w0);      // #== w0
        const int w1 = w0 + 1;
        int e = (tv.x == w1) + (tv.y == w1) + (tv.z == w1) + (tv.w == w1);      // #== w1
        int p = c | (d << 10) | (e << 20);      // fields <= 512 < 1024, no carry
        p = __reduce_add_sync(0xffffffffu, p);
        if ((h & 31) == 0) s_part[h >> 5] = p;
    }
    __syncthreads();
    const int sum  = s_part[0] + s_part[1] + s_part[2] + s_part[3];  // broadcast LDS
    const int c    =  sum         & 1023;
    const int d    = (sum >> 10)  & 1023;
    const int e    = (sum >> 20)  & 1023;
    const int lo   = up ? (c + d) : c;
    const int cnt  = up ? e : d;
    const float inv = (cnt > 0) ? (1.0f / (float)cnt) : 0.0f;

    float4* orow = reinterpret_cast<float4*>(out + (size_t)bw * OUTW);

    const float4* rbase = reinterpret_cast<const float4*>(hidden + (size_t)b * SS * HH)
                          + (size_t)lo * HV;
    const bool has2 = (h < (HV - 128));     // h < 64
    const float4 z = make_float4(0.f, 0.f, 0.f, 0.f);

    // ---- depth-4 predicated prefetch, both chains, before any FADD ----
    const float4* c0 = rbase + h;
    const float4* c1 = rbase + h + 128;
    float4 t0 = (cnt > 0) ? __ldcs(c0 + 0 * HV) : z;
    float4 t1 = (cnt > 1) ? __ldcs(c0 + 1 * HV) : z;
    float4 t2 = (cnt > 2) ? __ldcs(c0 + 2 * HV) : z;
    float4 t3 = (cnt > 3) ? __ldcs(c0 + 3 * HV) : z;
    float4 u0 = (has2 && cnt > 0) ? __ldcs(c1 + 0 * HV) : z;
    float4 u1 = (has2 && cnt > 1) ? __ldcs(c1 + 1 * HV) : z;
    float4 u2 = (has2 && cnt > 2) ? __ldcs(c1 + 2 * HV) : z;
    float4 u3 = (has2 && cnt > 3) ? __ldcs(c1 + 3 * HV) : z;

    float4 a0, a1;
    a0.x = (t0.x + t1.x) + (t2.x + t3.x);
    a0.y = (t0.y + t1.y) + (t2.y + t3.y);
    a0.z = (t0.z + t1.z) + (t2.z + t3.z);
    a0.w = (t0.w + t1.w) + (t2.w + t3.w);
    a1.x = (u0.x + u1.x) + (u2.x + u3.x);
    a1.y = (u0.y + u1.y) + (u2.y + u3.y);
    a1.z = (u0.z + u1.z) + (u2.z + u3.z);
    a1.w = (u0.w + u1.w) + (u2.w + u3.w);

    // ---- rare remainder (cnt > 4) ----
    #pragma unroll 1
    for (int s = 4; s < cnt; ++s) {
        float4 v0 = __ldcs(c0 + (size_t)s * HV);
        a0.x += v0.x; a0.y += v0.y; a0.z += v0.z; a0.w += v0.w;
        if (has2) {
            float4 v1 = __ldcs(c1 + (size_t)s * HV);
            a1.x += v1.x; a1.y += v1.y; a1.z += v1.z; a1.w += v1.w;
        }
    }

    a0.x *= inv; a0.y *= inv; a0.z *= inv; a0.w *= inv;
    __stcs(&orow[h], a0);
    if (has2) {
        a1.x *= inv; a1.y *= inv; a1.z *= inv; a1.w *= inv;
        __stcs(&orow[h + 128], a1);
    }
    if (hasw) {
        __stcs(&orow[HV + h], gv);
    }
}

extern "C" void kernel_launch(void* const* d_in, const int* in_sizes, int n_in,
                              void* d_out, int out_size)
{
    // Identify inputs by element count (robust to ordering):
    //   hidden    : 64*512*768  = 25,165,824 (float32)
    //   w2v_table : 50000*300   = 15,000,000 (float32)
    //   token_ids : 64*512      = 32,768     (int32)
    //   word_ids  : 64*256      = 16,384     (int32)
    const float* hidden = nullptr;
    const float* w2v    = nullptr;
    const int*   tok    = nullptr;
    const int*   wids   = nullptr;
    for (int i = 0; i < n_in; ++i) {
        switch (in_sizes[i]) {
            case 25165824: hidden = (const float*)d_in[i]; break;
            case 15000000: w2v    = (const float*)d_in[i]; break;
            case 32768:    tok    = (const int*)d_in[i];   break;
            case 16384:    wids   = (const int*)d_in[i];   break;
            default: break;
        }
    }
    float* out = (float*)d_out;

    embeddings_fused_kernel<<<(BB * WW) / 2, 256>>>(hidden, w2v, tok, wids, out);
}